// round 1
// baseline (speedup 1.0000x reference)
#include <cuda_runtime.h>
#include <math.h>

#define N_PTS   32768
#define KCODES  2048
#define DIM     128
#define BM      128
#define BK      128
#define XS      132                 // smem row stride (floats), 16B-aligned
#define TEMP_INV (1.0f/0.9f)

// Scratch (allocation-free rule: __device__ globals)
__device__ float g_conf[(size_t)N_PTS * KCODES];   // 256 MB conf' spill
__device__ float g_maxv[N_PTS];
__device__ float g_esq[KCODES];
__device__ float g_clsum[KCODES];

// ---------------------------------------------------------------------------
// Kernel 1: e_sq per code (warp per code) + zero the class-prob accumulators.
// ---------------------------------------------------------------------------
__global__ void prep_kernel(const float* __restrict__ embed) {
    int gtid = blockIdx.x * blockDim.x + threadIdx.x;
    if (gtid < KCODES) g_clsum[gtid] = 0.f;
    int warp = gtid >> 5;
    int lane = gtid & 31;
    if (warp < KCODES) {
        const float* row = embed + (size_t)warp * DIM;
        float s = 0.f;
        #pragma unroll
        for (int i = 0; i < 4; ++i) { float v = row[lane + 32 * i]; s = fmaf(v, v, s); }
        #pragma unroll
        for (int o = 16; o > 0; o >>= 1) s += __shfl_down_sync(0xffffffffu, s, o);
        if (lane == 0) g_esq[warp] = s;
    }
}

// ---------------------------------------------------------------------------
// Kernel 2: tiled fp32 GEMM conf' = 2*x.e - e_sq, running per-point argmax,
// conf' spill to scratch, fused gather of quantize rows + embed_ind write.
// Block: 256 threads, BM=128 points x all K (16 k-tiles of BK=128).
// ---------------------------------------------------------------------------
__global__ void gemm_kernel(const float* __restrict__ x,
                            const float* __restrict__ embed,
                            float* __restrict__ out_q,
                            float* __restrict__ out_ind) {
    extern __shared__ float sm[];
    float* xs = sm;                  // [DIM][XS]  x tile, d-major (transposed)
    float* es = sm + DIM * XS;       // [DIM][XS]  embed tile, d-major

    const int tid = threadIdx.x;
    const int tx  = tid & 15;        // code-block column  (8 codes)
    const int ty  = tid >> 4;        // point-block row    (8 points)
    const int n0  = blockIdx.x * BM;

    // Load x tile transposed: xs[d][m] = x[(n0+m)*DIM + d]
    {
        const float4* x4 = (const float4*)(x + (size_t)n0 * DIM);
        for (int idx = tid; idx < BM * (DIM / 4); idx += 256) {
            int m  = idx >> 5;       // 0..127
            int d4 = idx & 31;       // float4 index along d
            float4 v = x4[m * 32 + d4];
            int d = d4 * 4;
            xs[(d + 0) * XS + m] = v.x;
            xs[(d + 1) * XS + m] = v.y;
            xs[(d + 2) * XS + m] = v.z;
            xs[(d + 3) * XS + m] = v.w;
        }
    }

    float runv[8];
    int   runi[8];
    #pragma unroll
    for (int i = 0; i < 8; ++i) { runv[i] = -3.0e38f; runi[i] = 0; }

    for (int kt = 0; kt < KCODES; kt += BK) {
        __syncthreads();
        // Load embed tile transposed: es[d][k] = embed[(kt+k)*DIM + d]
        {
            const float4* e4 = (const float4*)(embed + (size_t)kt * DIM);
            for (int idx = tid; idx < BK * (DIM / 4); idx += 256) {
                int m  = idx >> 5;
                int d4 = idx & 31;
                float4 v = e4[m * 32 + d4];
                int d = d4 * 4;
                es[(d + 0) * XS + m] = v.x;
                es[(d + 1) * XS + m] = v.y;
                es[(d + 2) * XS + m] = v.z;
                es[(d + 3) * XS + m] = v.w;
            }
        }
        __syncthreads();

        float acc[8][8];
        #pragma unroll
        for (int i = 0; i < 8; ++i)
            #pragma unroll
            for (int j = 0; j < 8; ++j) acc[i][j] = 0.f;

        #pragma unroll 4
        for (int d = 0; d < DIM; ++d) {
            float4 a0 = *(const float4*)&xs[d * XS + ty * 8];
            float4 a1 = *(const float4*)&xs[d * XS + ty * 8 + 4];
            float4 b0 = *(const float4*)&es[d * XS + tx * 8];
            float4 b1 = *(const float4*)&es[d * XS + tx * 8 + 4];
            float a[8] = {a0.x, a0.y, a0.z, a0.w, a1.x, a1.y, a1.z, a1.w};
            float b[8] = {b0.x, b0.y, b0.z, b0.w, b1.x, b1.y, b1.z, b1.w};
            #pragma unroll
            for (int i = 0; i < 8; ++i)
                #pragma unroll
                for (int j = 0; j < 8; ++j)
                    acc[i][j] = fmaf(a[i], b[j], acc[i][j]);
        }

        float eq[8];
        #pragma unroll
        for (int j = 0; j < 8; ++j) eq[j] = g_esq[kt + tx * 8 + j];

        #pragma unroll
        for (int i = 0; i < 8; ++i) {
            float c[8];
            #pragma unroll
            for (int j = 0; j < 8; ++j) {
                c[j] = fmaf(2.f, acc[i][j], -eq[j]);
                // strict > and ascending k => first-max tie-break (jnp.argmax)
                if (c[j] > runv[i]) { runv[i] = c[j]; runi[i] = kt + tx * 8 + j; }
            }
            float* dst = &g_conf[(size_t)(n0 + ty * 8 + i) * KCODES + kt + tx * 8];
            *(float4*)(dst)     = make_float4(c[0], c[1], c[2], c[3]);
            *(float4*)(dst + 4) = make_float4(c[4], c[5], c[6], c[7]);
        }
    }

    // Cross-thread argmax reduction (16 column-threads per point)
    __syncthreads();
    float* red_v = sm;                       // [BM][16]
    int*   red_i = (int*)(sm + BM * 16);     // [BM][16]
    int*   sidx  = (int*)(sm + BM * 32);     // [BM]
    #pragma unroll
    for (int i = 0; i < 8; ++i) {
        red_v[(ty * 8 + i) * 16 + tx] = runv[i];
        red_i[(ty * 8 + i) * 16 + tx] = runi[i];
    }
    __syncthreads();
    if (tid < BM) {
        float bv = red_v[tid * 16];
        int   bi = red_i[tid * 16];
        #pragma unroll
        for (int t = 1; t < 16; ++t) {
            float v  = red_v[tid * 16 + t];
            int   ii = red_i[tid * 16 + t];
            if (v > bv || (v == bv && ii < bi)) { bv = v; bi = ii; }
        }
        g_maxv[n0 + tid]  = bv;
        sidx[tid]         = bi;
        out_ind[n0 + tid] = (float)bi;
    }
    __syncthreads();

    // Fused gather: quantize[n] = embed[argmax]. One warp copies a 512B row.
    {
        int lane = tid & 31, w = tid >> 5;
        const float4* e4 = (const float4*)embed;
        float4*       q4 = (float4*)out_q;
        for (int p = w; p < BM; p += 8) {
            int idx = sidx[p];
            q4[(size_t)(n0 + p) * 32 + lane] = e4[(size_t)idx * 32 + lane];
        }
    }
}

// ---------------------------------------------------------------------------
// Kernel 3: per-point softmax Z + class-prob accumulation.
// 8 points/block (warp per point), exps staged in 64KB smem, threshold-skip
// of negligible exps (warp-uniform guard), RED-atomics into 2048 bins.
// ---------------------------------------------------------------------------
__global__ void softmax_kernel() {
    extern __shared__ float eb[];            // [8][KCODES]
    __shared__ float zinv_s[8];
    const int tid  = threadIdx.x;
    const int lane = tid & 31;
    const int w    = tid >> 5;
    const int n    = blockIdx.x * 8 + w;

    const float m = g_maxv[n];
    const float* row = &g_conf[(size_t)n * KCODES];

    float z = 0.f;
    for (int j = 0; j < KCODES / 32; ++j) {
        int k = j * 32 + lane;
        float t = (row[k] - m) * TEMP_INV;    // <= 0
        float ex = 0.f;
        if (__any_sync(0xffffffffu, t > -17.f)) {
            ex = (t > -17.f) ? __expf(t) : 0.f;
        }
        eb[w * KCODES + k] = ex;
        z += ex;
    }
    #pragma unroll
    for (int o = 16; o > 0; o >>= 1) z += __shfl_down_sync(0xffffffffu, z, o);
    if (lane == 0) zinv_s[w] = 1.f / z;       // z >= 1 (argmax term)
    __syncthreads();

    for (int k = tid; k < KCODES; k += 256) {
        float s = 0.f;
        #pragma unroll
        for (int ww = 0; ww < 8; ++ww) s = fmaf(eb[ww * KCODES + k], zinv_s[ww], s);
        atomicAdd(&g_clsum[k], s);            // RED.F32 to 2048 spread bins
    }
}

// ---------------------------------------------------------------------------
// Kernel 4: diversity loss = sum_k p_k * log(p_k + eps), p_k = clsum_k / N.
// ---------------------------------------------------------------------------
__global__ void loss_kernel(float* __restrict__ out_loss) {
    __shared__ float red[256];
    const int tid = threadIdx.x;
    float acc = 0.f;
    for (int k = tid; k < KCODES; k += 256) {
        float p = g_clsum[k] * (1.0f / (float)N_PTS);
        acc += p * logf(p + 1e-6f);
    }
    red[tid] = acc;
    __syncthreads();
    for (int s = 128; s > 0; s >>= 1) {
        if (tid < s) red[tid] += red[tid + s];
        __syncthreads();
    }
    if (tid == 0) *out_loss = red[0];
}

// ---------------------------------------------------------------------------
extern "C" void kernel_launch(void* const* d_in, const int* in_sizes, int n_in,
                              void* d_out, int out_size) {
    const float* x     = (const float*)d_in[0];
    const float* embed = (const float*)d_in[1];
    float* out      = (float*)d_out;
    float* out_q    = out;                                   // N*DIM
    float* out_ind  = out + (size_t)N_PTS * DIM;             // N
    float* out_loss = out + (size_t)N_PTS * DIM + N_PTS;     // 1

    const int gemm_smem = 2 * DIM * XS * (int)sizeof(float);     // 132 KB
    const int smax_smem = 8 * KCODES * (int)sizeof(float);       // 64 KB
    cudaFuncSetAttribute(gemm_kernel,    cudaFuncAttributeMaxDynamicSharedMemorySize, gemm_smem);
    cudaFuncSetAttribute(softmax_kernel, cudaFuncAttributeMaxDynamicSharedMemorySize, smax_smem);

    prep_kernel   <<<256, 256>>>(embed);
    gemm_kernel   <<<N_PTS / BM, 256, gemm_smem>>>(x, embed, out_q, out_ind);
    softmax_kernel<<<N_PTS / 8, 256, smax_smem>>>();
    loss_kernel   <<<1, 256>>>(out_loss);
}

// round 2
// speedup vs baseline: 1.4426x; 1.4426x over previous
#include <cuda_runtime.h>
#include <math.h>

#define N_PTS   32768
#define KCODES  2048
#define DIM     128
#define BM      128
#define BN      64
#define SA      132                 // smem row stride (floats)
#define TEMP_INV (1.0f/0.9f)

// Scratch (allocation-free rule: __device__ globals)
__device__ float g_conf[(size_t)N_PTS * KCODES];   // 256 MB conf' spill
__device__ float g_maxv[N_PTS];
__device__ float g_esq[KCODES];
__device__ float g_clsum[KCODES];

__device__ __forceinline__ float tf32r(float a) {
    float r;
    asm("cvt.rna.tf32.f32 %0, %1;" : "=f"(r) : "f"(a));
    return r;
}

#define MMA_TF32(d, a, b) \
    asm volatile("mma.sync.aligned.m16n8k8.row.col.f32.tf32.tf32.f32 " \
        "{%0,%1,%2,%3},{%4,%5,%6,%7},{%8,%9},{%0,%1,%2,%3};" \
        : "+f"((d)[0]), "+f"((d)[1]), "+f"((d)[2]), "+f"((d)[3]) \
        : "r"(__float_as_uint((a)[0])), "r"(__float_as_uint((a)[1])), \
          "r"(__float_as_uint((a)[2])), "r"(__float_as_uint((a)[3])), \
          "r"(__float_as_uint((b)[0])), "r"(__float_as_uint((b)[1])))

// ---------------------------------------------------------------------------
// Kernel 1: e_sq per code (warp per code) + zero class-prob accumulators.
// ---------------------------------------------------------------------------
__global__ void prep_kernel(const float* __restrict__ embed) {
    int gtid = blockIdx.x * blockDim.x + threadIdx.x;
    if (gtid < KCODES) g_clsum[gtid] = 0.f;
    int warp = gtid >> 5;
    int lane = gtid & 31;
    if (warp < KCODES) {
        const float* row = embed + (size_t)warp * DIM;
        float s = 0.f;
        #pragma unroll
        for (int i = 0; i < 4; ++i) { float v = row[lane + 32 * i]; s = fmaf(v, v, s); }
        #pragma unroll
        for (int o = 16; o > 0; o >>= 1) s += __shfl_down_sync(0xffffffffu, s, o);
        if (lane == 0) g_esq[warp] = s;
    }
}

// ---------------------------------------------------------------------------
// Kernel 2: 3xTF32 tensor-core GEMM conf' = (2x).e - e_sq + running argmax
// + conf spill + fused gather + ind write.
// CTA: 256 thr (8 warps, 4x2), tile 128 pts x 64 codes, K=128 resident.
// smem: A_hi/A_lo [128][SA], B_hi/B_lo [64][SA]  (fp32-in-tf32 splits)
// ---------------------------------------------------------------------------
__global__ void __launch_bounds__(256, 1)
gemm_kernel(const float* __restrict__ x,
            const float* __restrict__ embed,
            float* __restrict__ out_q,
            float* __restrict__ out_ind) {
    extern __shared__ float sm[];
    float* a_hi = sm;
    float* a_lo = a_hi + BM * SA;
    float* b_hi = a_lo + BM * SA;
    float* b_lo = b_hi + BN * SA;

    const int tid  = threadIdx.x;
    const int lane = tid & 31;
    const int w    = tid >> 5;
    const int wm   = w >> 1;          // 0..3: 32-point slab
    const int wn   = w & 1;           // 0..1: 32-code slab
    const int n0   = blockIdx.x * BM;

    // ---- A split (x scaled by 2, exact): a_hi/a_lo[m][k] ----
    {
        const float4* x4 = (const float4*)(x + (size_t)n0 * DIM);
        for (int idx = tid; idx < BM * (DIM / 4); idx += 256) {
            int m = idx >> 5, k4 = idx & 31;
            float4 v = x4[idx];
            float a[4] = {2.f * v.x, 2.f * v.y, 2.f * v.z, 2.f * v.w};
            #pragma unroll
            for (int j = 0; j < 4; ++j) {
                float hi = tf32r(a[j]);
                float lo = tf32r(a[j] - hi);
                a_hi[m * SA + k4 * 4 + j] = hi;
                a_lo[m * SA + k4 * 4 + j] = lo;
            }
        }
    }

    float runv[4];
    int   runi[4];
    #pragma unroll
    for (int i = 0; i < 4; ++i) { runv[i] = -3.0e38f; runi[i] = 0; }

    for (int ct = 0; ct < KCODES / BN; ++ct) {
        const int c0 = ct * BN;
        __syncthreads();
        // ---- B split: b_hi/b_lo[n][k] from embed rows c0..c0+63 ----
        {
            const float4* e4 = (const float4*)(embed + (size_t)c0 * DIM);
            for (int idx = tid; idx < BN * (DIM / 4); idx += 256) {
                int n = idx >> 5, k4 = idx & 31;
                float4 v = e4[idx];
                float b[4] = {v.x, v.y, v.z, v.w};
                #pragma unroll
                for (int j = 0; j < 4; ++j) {
                    float hi = tf32r(b[j]);
                    float lo = tf32r(b[j] - hi);
                    b_hi[n * SA + k4 * 4 + j] = hi;
                    b_lo[n * SA + k4 * 4 + j] = lo;
                }
            }
        }
        __syncthreads();

        float acc[2][4][4];
        #pragma unroll
        for (int mt = 0; mt < 2; ++mt)
            #pragma unroll
            for (int nt = 0; nt < 4; ++nt)
                #pragma unroll
                for (int r = 0; r < 4; ++r) acc[mt][nt][r] = 0.f;

        #pragma unroll
        for (int ks = 0; ks < DIM / 8; ++ks) {
            const int kk = ks * 8;
            float ah[2][4], al[2][4];
            #pragma unroll
            for (int mt = 0; mt < 2; ++mt) {
                int row = wm * 32 + mt * 16 + (lane >> 2);
                int col = kk + (lane & 3);
                ah[mt][0] = a_hi[row * SA + col];
                ah[mt][1] = a_hi[(row + 8) * SA + col];
                ah[mt][2] = a_hi[row * SA + col + 4];
                ah[mt][3] = a_hi[(row + 8) * SA + col + 4];
                al[mt][0] = a_lo[row * SA + col];
                al[mt][1] = a_lo[(row + 8) * SA + col];
                al[mt][2] = a_lo[row * SA + col + 4];
                al[mt][3] = a_lo[(row + 8) * SA + col + 4];
            }
            float bh[4][2], bl[4][2];
            #pragma unroll
            for (int nt = 0; nt < 4; ++nt) {
                int nr = wn * 32 + nt * 8 + (lane >> 2);
                int kc = kk + (lane & 3);
                bh[nt][0] = b_hi[nr * SA + kc];
                bh[nt][1] = b_hi[nr * SA + kc + 4];
                bl[nt][0] = b_lo[nr * SA + kc];
                bl[nt][1] = b_lo[nr * SA + kc + 4];
            }
            #pragma unroll
            for (int mt = 0; mt < 2; ++mt)
                #pragma unroll
                for (int nt = 0; nt < 4; ++nt) {
                    MMA_TF32(acc[mt][nt], ah[mt], bh[nt]);   // hi*hi
                    MMA_TF32(acc[mt][nt], ah[mt], bl[nt]);   // hi*lo
                    MMA_TF32(acc[mt][nt], al[mt], bh[nt]);   // lo*hi
                }
        }

        // ---- epilogue: conf = acc - esq, argmax (ascending code order), spill ----
        #pragma unroll
        for (int nt = 0; nt < 4; ++nt) {
            int cb = c0 + wn * 32 + nt * 8 + 2 * (lane & 3);
            float e0 = __ldg(&g_esq[cb]);
            float e1 = __ldg(&g_esq[cb + 1]);
            #pragma unroll
            for (int mt = 0; mt < 2; ++mt) {
                #pragma unroll
                for (int h = 0; h < 2; ++h) {
                    int slot = mt * 2 + h;
                    int row  = n0 + wm * 32 + mt * 16 + (lane >> 2) + h * 8;
                    float v0 = acc[mt][nt][2 * h + 0] - e0;
                    float v1 = acc[mt][nt][2 * h + 1] - e1;
                    if (v0 > runv[slot]) { runv[slot] = v0; runi[slot] = cb; }
                    if (v1 > runv[slot]) { runv[slot] = v1; runi[slot] = cb + 1; }
                    *(float2*)&g_conf[(size_t)row * KCODES + cb] = make_float2(v0, v1);
                }
            }
        }
    }

    // ---- cross-thread argmax reduction: 8 contributors per point row ----
    __syncthreads();
    float* red_v = sm;                         // [BM][8]
    int*   red_i = (int*)(sm + BM * 8);        // [BM][8]
    int*   sidx  = (int*)(sm + BM * 16);       // [BM]
    #pragma unroll
    for (int mt = 0; mt < 2; ++mt)
        #pragma unroll
        for (int h = 0; h < 2; ++h) {
            int slot = mt * 2 + h;
            int rloc = wm * 32 + mt * 16 + (lane >> 2) + h * 8;
            int cidx = wn * 4 + (lane & 3);
            red_v[rloc * 8 + cidx] = runv[slot];
            red_i[rloc * 8 + cidx] = runi[slot];
        }
    __syncthreads();
    if (tid < BM) {
        float bv = red_v[tid * 8];
        int   bi = red_i[tid * 8];
        #pragma unroll
        for (int t = 1; t < 8; ++t) {
            float v  = red_v[tid * 8 + t];
            int   ii = red_i[tid * 8 + t];
            if (v > bv || (v == bv && ii < bi)) { bv = v; bi = ii; }
        }
        g_maxv[n0 + tid]  = bv;
        sidx[tid]         = bi;
        out_ind[n0 + tid] = (float)bi;
    }
    __syncthreads();

    // ---- fused gather: one warp copies one 512B codebook row per point ----
    {
        const float4* e4 = (const float4*)embed;
        float4*       q4 = (float4*)out_q;
        for (int p = w; p < BM; p += 8) {
            int idx = sidx[p];
            q4[(size_t)(n0 + p) * 32 + lane] = e4[(size_t)idx * 32 + lane];
        }
    }
}

// ---------------------------------------------------------------------------
// Kernel 3: per-point softmax Z + class-prob accumulation.
// ---------------------------------------------------------------------------
__global__ void softmax_kernel() {
    extern __shared__ float eb[];            // [8][KCODES]
    __shared__ float zinv_s[8];
    const int tid  = threadIdx.x;
    const int lane = tid & 31;
    const int w    = tid >> 5;
    const int n    = blockIdx.x * 8 + w;

    const float m = g_maxv[n];
    const float* row = &g_conf[(size_t)n * KCODES];

    float z = 0.f;
    for (int j = 0; j < KCODES / 32; ++j) {
        int k = j * 32 + lane;
        float t = (row[k] - m) * TEMP_INV;    // <= 0
        float ex = 0.f;
        if (__any_sync(0xffffffffu, t > -17.f)) {
            ex = (t > -17.f) ? __expf(t) : 0.f;
        }
        eb[w * KCODES + k] = ex;
        z += ex;
    }
    #pragma unroll
    for (int o = 16; o > 0; o >>= 1) z += __shfl_down_sync(0xffffffffu, z, o);
    if (lane == 0) zinv_s[w] = 1.f / z;       // z >= 1 (argmax term)
    __syncthreads();

    for (int k = tid; k < KCODES; k += 256) {
        float s = 0.f;
        #pragma unroll
        for (int ww = 0; ww < 8; ++ww) s = fmaf(eb[ww * KCODES + k], zinv_s[ww], s);
        atomicAdd(&g_clsum[k], s);
    }
}

// ---------------------------------------------------------------------------
// Kernel 4: diversity loss = sum_k p_k * log(p_k + eps).
// ---------------------------------------------------------------------------
__global__ void loss_kernel(float* __restrict__ out_loss) {
    __shared__ float red[256];
    const int tid = threadIdx.x;
    float acc = 0.f;
    for (int k = tid; k < KCODES; k += 256) {
        float p = g_clsum[k] * (1.0f / (float)N_PTS);
        acc += p * logf(p + 1e-6f);
    }
    red[tid] = acc;
    __syncthreads();
    for (int s = 128; s > 0; s >>= 1) {
        if (tid < s) red[tid] += red[tid + s];
        __syncthreads();
    }
    if (tid == 0) *out_loss = red[0];
}

// ---------------------------------------------------------------------------
extern "C" void kernel_launch(void* const* d_in, const int* in_sizes, int n_in,
                              void* d_out, int out_size) {
    const float* x     = (const float*)d_in[0];
    const float* embed = (const float*)d_in[1];
    float* out      = (float*)d_out;
    float* out_q    = out;                                   // N*DIM
    float* out_ind  = out + (size_t)N_PTS * DIM;             // N
    float* out_loss = out + (size_t)N_PTS * DIM + N_PTS;     // 1

    const int gemm_smem = (2 * BM * SA + 2 * BN * SA) * (int)sizeof(float);  // ~198 KB
    const int smax_smem = 8 * KCODES * (int)sizeof(float);                   // 64 KB
    cudaFuncSetAttribute(gemm_kernel,    cudaFuncAttributeMaxDynamicSharedMemorySize, gemm_smem);
    cudaFuncSetAttribute(softmax_kernel, cudaFuncAttributeMaxDynamicSharedMemorySize, smax_smem);

    prep_kernel   <<<256, 256>>>(embed);
    gemm_kernel   <<<N_PTS / BM, 256, gemm_smem>>>(x, embed, out_q, out_ind);
    softmax_kernel<<<N_PTS / 8, 256, smax_smem>>>();
    loss_kernel   <<<1, 256>>>(out_loss);
}